// round 2
// baseline (speedup 1.0000x reference)
#include <cuda_runtime.h>
#include <math.h>

#define NN   50000
#define EE   800000
#define HD   256
#define LL   4
#define H2   512
#define DOUT 2
#define BNEPS 1e-5f

// ---------------- scratch (no allocations allowed) ----------------
__device__ float g_buf0[(size_t)NN * HD];
__device__ float g_buf1[(size_t)NN * HD];
__device__ float g_buf2[(size_t)NN * HD];
__device__ float g_mlp [(size_t)NN * H2];
__device__ float g_deg [NN];
__device__ float g_bnsum[2 * HD];   // [0:256) sum, [256:512) sumsq
__device__ float g_bnsc [HD];       // gamma * rstd
__device__ float g_bnsh [HD];       // beta - mu * gamma * rstd

// ---------------- small utility kernels ----------------
__global__ void k_zero4(float4* p, int n4) {
    int i = blockIdx.x * blockDim.x + threadIdx.x;
    if (i < n4) p[i] = make_float4(0.f, 0.f, 0.f, 0.f);
}

__global__ void k_deg_count(const int* __restrict__ dst, float* __restrict__ deg, int e) {
    int i = blockIdx.x * blockDim.x + threadIdx.x;
    if (i < e) atomicAdd(&deg[dst[i]], 1.0f);
}

__global__ void k_deg_inv(float* deg, int n) {
    int i = blockIdx.x * blockDim.x + threadIdx.x;
    if (i < n) deg[i] = 1.0f / fmaxf(deg[i], 1.0f);
}

// agg[dst] += h[src], one float4 chunk per thread, vectorized L2 reduction
__global__ void k_scatter(const float4* __restrict__ h, const int* __restrict__ src,
                          const int* __restrict__ dst, float* __restrict__ agg) {
    long long i = (long long)blockIdx.x * blockDim.x + threadIdx.x;
    long long total = (long long)EE * 64;
    if (i >= total) return;
    int e = (int)(i >> 6);
    int g = (int)(i & 63);
    int s = src[e], d = dst[e];
    float4 v = h[(size_t)s * 64 + g];
    float* o = agg + (size_t)d * HD + g * 4;
    asm volatile("red.global.add.v4.f32 [%0], {%1, %2, %3, %4};"
                 :: "l"(o), "f"(v.x), "f"(v.y), "f"(v.z), "f"(v.w) : "memory");
}

// column sums / sumsq over [NN, 256], chunked rows + block-level atomics
__global__ void k_bn_reduce(const float* __restrict__ x, float* __restrict__ sums) {
    int col = threadIdx.x;               // 0..255
    int r0 = blockIdx.x * 128;
    int rend = min(r0 + 128, NN);
    float s = 0.f, q = 0.f;
    for (int r = r0; r < rend; r++) {
        float v = x[(size_t)r * HD + col];
        s += v;
        q += v * v;
    }
    atomicAdd(&sums[col], s);
    atomicAdd(&sums[HD + col], q);
}

__global__ void k_bn_final(const float* __restrict__ sums, const float* __restrict__ g,
                           const float* __restrict__ b, float* __restrict__ sc,
                           float* __restrict__ sh) {
    int c = threadIdx.x;
    float mu  = sums[c] * (1.0f / NN);
    float var = sums[HD + c] * (1.0f / NN) - mu * mu;
    float rstd = rsqrtf(var + BNEPS);
    float s = g[c] * rstd;
    sc[c] = s;
    sh[c] = b[c] - mu * s;
}

// ---------------- generic NT GEMM: C = A*W^T (+ A2*W2^T) + bias, epilogues ----------------
// EPI 0: relu(acc + bias)
// EPI 1: acc + bias
// EPI 2: acc + bias + relu(aux * bn_sc + bn_sh)   (skip + fused BN+ReLU)
// Optional rowscale rs[]: A rows (pass 0 only) are multiplied by rs[row] on load.
template <int EPI, bool DUAL, bool RS>
__global__ void __launch_bounds__(256, 2)
k_gemm(const float* __restrict__ A, const float* __restrict__ W,
       const float* __restrict__ A2, const float* __restrict__ W2,
       const float* __restrict__ bias,
       const float* __restrict__ bn_sc, const float* __restrict__ bn_sh,
       const float* __restrict__ aux, const float* __restrict__ rs,
       float* __restrict__ C, int M, int Nc, int K) {
    constexpr int BM = 128, BN = 128, BK = 16;
    __shared__ float As[BK][BM + 4];
    __shared__ float Ws[BK][BN + 4];

    const int tid = threadIdx.x;
    const int tx = tid & 15;        // col group: 8 cols
    const int ty = tid >> 4;        // row group: 8 rows
    const int m0 = blockIdx.y * BM;
    const int n0 = blockIdx.x * BN;
    const int lr = tid >> 2;        // 0..63
    const int lc = (tid & 3) * 4;   // 0,4,8,12

    const int itersPerPass = K / BK;
    const int totalIters = (DUAL ? 2 : 1) * itersPerPass;

    float acc[8][8];
#pragma unroll
    for (int i = 0; i < 8; i++)
#pragma unroll
        for (int j = 0; j < 8; j++) acc[i][j] = 0.f;

    float4 ra[2], rw[2];

    // stage loader: iteration it -> registers
    auto stage = [&](int it) {
        int pass = DUAL ? (it / itersPerPass) : 0;
        int k0 = (it - pass * itersPerPass) * BK;
        const float* Ap = pass ? A2 : A;
        const float* Wp = pass ? W2 : W;
#pragma unroll
        for (int half = 0; half < 2; half++) {
            int row = m0 + half * 64 + lr;
            float4 av = make_float4(0.f, 0.f, 0.f, 0.f);
            if (row < M) {
                av = *(const float4*)&Ap[(size_t)row * K + k0 + lc];
                if (RS && pass == 0) {
                    float s = rs[row];
                    av.x *= s; av.y *= s; av.z *= s; av.w *= s;
                }
            }
            ra[half] = av;
            rw[half] = *(const float4*)&Wp[(size_t)(n0 + half * 64 + lr) * K + k0 + lc];
        }
    };

    stage(0);
    for (int it = 0; it < totalIters; ++it) {
        // commit staged tile to smem
#pragma unroll
        for (int half = 0; half < 2; half++) {
            As[lc + 0][half * 64 + lr] = ra[half].x;
            As[lc + 1][half * 64 + lr] = ra[half].y;
            As[lc + 2][half * 64 + lr] = ra[half].z;
            As[lc + 3][half * 64 + lr] = ra[half].w;
            Ws[lc + 0][half * 64 + lr] = rw[half].x;
            Ws[lc + 1][half * 64 + lr] = rw[half].y;
            Ws[lc + 2][half * 64 + lr] = rw[half].z;
            Ws[lc + 3][half * 64 + lr] = rw[half].w;
        }
        __syncthreads();
        if (it + 1 < totalIters) stage(it + 1);   // prefetch next into regs
#pragma unroll
        for (int k = 0; k < BK; k++) {
            float4 a0 = *(const float4*)&As[k][ty * 8 + 0];
            float4 a1 = *(const float4*)&As[k][ty * 8 + 4];
            float4 b0 = *(const float4*)&Ws[k][tx * 8 + 0];
            float4 b1 = *(const float4*)&Ws[k][tx * 8 + 4];
            float ar[8] = {a0.x, a0.y, a0.z, a0.w, a1.x, a1.y, a1.z, a1.w};
            float br[8] = {b0.x, b0.y, b0.z, b0.w, b1.x, b1.y, b1.z, b1.w};
#pragma unroll
            for (int i = 0; i < 8; i++)
#pragma unroll
                for (int j = 0; j < 8; j++) acc[i][j] = fmaf(ar[i], br[j], acc[i][j]);
        }
        __syncthreads();
    }

    // epilogue (vectorized stores)
#pragma unroll
    for (int i = 0; i < 8; i++) {
        int m = m0 + ty * 8 + i;
        if (m >= M) continue;
#pragma unroll
        for (int jj = 0; jj < 2; jj++) {
            int n = n0 + tx * 8 + jj * 4;
            float4 v;
            float* vp = &v.x;
            float4 xx;
            if (EPI == 2) xx = *(const float4*)&aux[(size_t)m * Nc + n];
            const float* xp = &xx.x;
#pragma unroll
            for (int t = 0; t < 4; t++) {
                float val = acc[i][jj * 4 + t] + bias[n + t];
                if (EPI == 0) val = fmaxf(val, 0.f);
                if (EPI == 2) val += fmaxf(fmaf(xp[t], bn_sc[n + t], bn_sh[n + t]), 0.f);
                vp[t] = val;
            }
            *(float4*)&C[(size_t)m * Nc + n] = v;
        }
    }
}

// ---------------- final head: [M,256] @ [2,256]^T + b, log_softmax ----------------
__global__ void k_out_lsm(const float* __restrict__ h, const float* __restrict__ w,
                          const float* __restrict__ b, float* __restrict__ out, int M) {
    int row = blockIdx.x * blockDim.y + threadIdx.y;
    if (row >= M) return;
    int lane = threadIdx.x;
    const float* hr = h + (size_t)row * HD;
    float s0 = 0.f, s1 = 0.f;
    for (int k = lane; k < HD; k += 32) {
        float v = hr[k];
        s0 = fmaf(v, w[k], s0);
        s1 = fmaf(v, w[HD + k], s1);
    }
#pragma unroll
    for (int o = 16; o; o >>= 1) {
        s0 += __shfl_down_sync(0xffffffffu, s0, o);
        s1 += __shfl_down_sync(0xffffffffu, s1, o);
    }
    if (lane == 0) {
        float z0 = s0 + b[0], z1 = s1 + b[1];
        float mx = fmaxf(z0, z1);
        float lse = mx + logf(expf(z0 - mx) + expf(z1 - mx));
        out[(size_t)row * 2 + 0] = z0 - lse;
        out[(size_t)row * 2 + 1] = z1 - lse;
    }
}

// ---------------- launch ----------------
extern "C" void kernel_launch(void* const* d_in, const int* in_sizes, int n_in,
                              void* d_out, int out_size) {
    const float* x     = (const float*)d_in[0];
    const int*   ei    = (const int*)  d_in[1];
    const float* in_w  = (const float*)d_in[2];
    const float* in_b  = (const float*)d_in[3];
    const float* cwl   = (const float*)d_in[4];
    const float* cbl   = (const float*)d_in[5];
    const float* cwr   = (const float*)d_in[6];
    const float* bng   = (const float*)d_in[7];
    const float* bnb   = (const float*)d_in[8];
    const float* skw   = (const float*)d_in[9];
    const float* skb   = (const float*)d_in[10];
    const float* mw1   = (const float*)d_in[11];
    const float* mb1   = (const float*)d_in[12];
    const float* mw2   = (const float*)d_in[13];
    const float* mb2   = (const float*)d_in[14];
    const float* outw  = (const float*)d_in[15];
    const float* outb  = (const float*)d_in[16];
    float* out = (float*)d_out;

    const int* src = ei;
    const int* dst = ei + EE;

    float *b0, *b1, *b2, *bt, *deg, *bns, *bsc, *bsh;
    cudaGetSymbolAddress((void**)&b0,  g_buf0);
    cudaGetSymbolAddress((void**)&b1,  g_buf1);
    cudaGetSymbolAddress((void**)&b2,  g_buf2);
    cudaGetSymbolAddress((void**)&bt,  g_mlp);
    cudaGetSymbolAddress((void**)&deg, g_deg);
    cudaGetSymbolAddress((void**)&bns, g_bnsum);
    cudaGetSymbolAddress((void**)&bsc, g_bnsc);
    cudaGetSymbolAddress((void**)&bsh, g_bnsh);

    const int TPB = 256;
    const long long feat4 = (long long)NN * 64;
    const int featBlocks = (int)((feat4 + TPB - 1) / TPB);
    const long long scat = (long long)EE * 64;
    const int scatBlocks = (int)((scat + TPB - 1) / TPB);
    const int bnChunks = (NN + 127) / 128;

    // degrees -> inverse degrees
    k_zero4<<<(NN / 4 + TPB - 1) / TPB, TPB>>>((float4*)deg, NN / 4);
    k_deg_count<<<(EE + TPB - 1) / TPB, TPB>>>(dst, deg, EE);
    k_deg_inv<<<(NN + TPB - 1) / TPB, TPB>>>(deg, NN);

    dim3 g256(HD / 128, (NN + 127) / 128);
    dim3 g512(H2 / 128, (NN + 127) / 128);

    // input projection + relu  -> b0
    k_gemm<0, false, false><<<g256, TPB>>>(x, in_w, nullptr, nullptr, in_b,
                                           nullptr, nullptr, nullptr, nullptr,
                                           b0, NN, HD, HD);

    float* bufs[3] = {b0, b1, b2};
    int hi = 0;
    for (int l = 0; l < LL; l++) {
        float* h   = bufs[hi];
        float* agg = bufs[(hi + 1) % 3];
        float* cv  = bufs[(hi + 2) % 3];

        k_zero4<<<featBlocks, TPB>>>((float4*)agg, (int)feat4);
        k_scatter<<<scatBlocks, TPB>>>((const float4*)h, src, dst, agg);

        // cv = (agg * invdeg) @ wl^T + h @ wr^T + bl   (deg-normalization fused into A-load)
        k_gemm<1, true, true><<<g256, TPB>>>(agg, cwl + (size_t)l * HD * HD,
                                             h,   cwr + (size_t)l * HD * HD,
                                             cbl + (size_t)l * HD,
                                             nullptr, nullptr, nullptr, deg,
                                             cv, NN, HD, HD);

        // batch-norm statistics on cv
        k_zero4<<<1, 128>>>((float4*)bns, 128);
        k_bn_reduce<<<bnChunks, HD>>>(cv, bns);
        k_bn_final<<<1, HD>>>(bns, bng + (size_t)l * HD, bnb + (size_t)l * HD, bsc, bsh);

        // cv = h @ skip_w^T + skip_b + relu(bn(cv))   (in-place aux read is per-element safe)
        k_gemm<2, false, false><<<g256, TPB>>>(h, skw + (size_t)l * HD * HD, nullptr, nullptr,
                                               skb + (size_t)l * HD, bsc, bsh, cv, nullptr,
                                               cv, NN, HD, HD);
        hi = (hi + 2) % 3;
    }

    float* h  = bufs[hi];
    float* h2 = bufs[(hi + 1) % 3];

    // MLP
    k_gemm<0, false, false><<<g512, TPB>>>(h, mw1, nullptr, nullptr, mb1,
                                           nullptr, nullptr, nullptr, nullptr,
                                           bt, NN, H2, HD);
    k_gemm<1, false, false><<<g256, TPB>>>(bt, mw2, nullptr, nullptr, mb2,
                                           nullptr, nullptr, nullptr, nullptr,
                                           h2, NN, HD, H2);

    // output head + log_softmax
    dim3 ob(32, 8);
    k_out_lsm<<<(NN + 7) / 8, ob>>>(h2, outw, outb, out, NN);
}